// round 5
// baseline (speedup 1.0000x reference)
#include <cuda_runtime.h>
#include <cuda_bf16.h>
#include <cstdint>

typedef unsigned long long u64;

// ---------------- constants ----------------
#define LSEQ     2048
#define DIMV     32
#define SEGS     4
#define SEG_ROWS 512
#define CHUNK_R  128
#define NCHUNK   4
#define NBUF     2
#define THREADS  256
#define NPAIRS   496
#define OUTW     528
#define ROWF     36                        // padded row: 36 floats = 144 B (bank shift 4/row)
#define ROWB     (ROWF * 4)                // 144
#define CHUNK_BYTES (CHUNK_R * ROWB)       // 18432

// partial C scratch: [B][SEGS][32*32] fp32 = 8 MB ; arrival counters
__device__ float g_part[512 * SEGS * 1024];
__device__ int   g_cnt[512];               // zero-initialized at module load; reset by combiner

// ---------------- f32x2 helpers ----------------
__device__ __forceinline__ u64 fma2(u64 a, u64 b, u64 c) {
    u64 d;
    asm("fma.rn.f32x2 %0, %1, %2, %3;" : "=l"(d) : "l"(a), "l"(b), "l"(c));
    return d;
}
__device__ __forceinline__ u64 add2(u64 a, u64 b) {
    u64 d;
    asm("add.rn.f32x2 %0, %1, %2;" : "=l"(d) : "l"(a), "l"(b));
    return d;
}
__device__ __forceinline__ u64 splat(float x) {
    u64 r;
    asm("mov.b64 %0, {%1, %1};" : "=l"(r) : "f"(x));
    return r;
}
__device__ __forceinline__ u64 pk2(float x, float y) {
    u64 r;
    asm("mov.b64 %0, {%1, %2};" : "=l"(r) : "f"(x), "f"(y));
    return r;
}

// ---------------- shared-memory access (32-bit addresses) ----------------
__device__ __forceinline__ void lds_v2u64(u64& b0, u64& b1, unsigned addr) {
    asm volatile("ld.shared.v2.b64 {%0, %1}, [%2];" : "=l"(b0), "=l"(b1) : "r"(addr));
}
__device__ __forceinline__ float4 lds_f4(unsigned addr) {
    float4 v;
    asm volatile("ld.shared.v4.f32 {%0, %1, %2, %3}, [%4];"
                 : "=f"(v.x), "=f"(v.y), "=f"(v.z), "=f"(v.w) : "r"(addr));
    return v;
}

// ---------------- cp.async ----------------
__device__ __forceinline__ void cp_commit() { asm volatile("cp.async.commit_group;"); }
template <int N>
__device__ __forceinline__ void cp_wait() { asm volatile("cp.async.wait_group %0;" ::"n"(N)); }

// copy one 128x32 fp32 chunk (16 KB gmem) into a padded smem buffer (144 B rows)
__device__ __forceinline__ void copy_chunk(const float* __restrict__ gseg,
                                           unsigned sb_addr, int c, int tid) {
    const char* gsrc = (const char*)(gseg + (size_t)c * CHUNK_R * DIMV);
#pragma unroll
    for (int i = 0; i < 4; i++) {
        int p   = tid + i * 256;            // 1024 pieces of 16 B
        int row = p >> 3;
        int sub = p & 7;
        unsigned dst = sb_addr + (unsigned)row * ROWB + (unsigned)sub * 16u;
        const char* src = gsrc + row * 128 + sub * 16;
        asm volatile("cp.async.cg.shared.global [%0], [%1], 16;" ::"r"(dst), "l"(src));
    }
}

// ---------------- macro step: 8x8 outer product (2 l-steps via h split) ----------
__device__ __forceinline__ void macro_b(u64* acc, u64 b0, u64 b1, u64 b2, u64 b3,
                                        float4 a0, float4 a1) {
    float av[8] = {a0.x, a0.y, a0.z, a0.w, a1.x, a1.y, a1.z, a1.w};
#pragma unroll
    for (int ii = 0; ii < 8; ii++) {
        u64 s = splat(av[ii]);
        acc[ii * 4 + 0] = fma2(s, b0, acc[ii * 4 + 0]);
        acc[ii * 4 + 1] = fma2(s, b1, acc[ii * 4 + 1]);
        acc[ii * 4 + 2] = fma2(s, b2, acc[ii * 4 + 2]);
        acc[ii * 4 + 3] = fma2(s, b3, acc[ii * 4 + 3]);
    }
}
__device__ __forceinline__ void macro_ab(u64* acc, unsigned aaddr, unsigned baddr) {
    float4 a0 = lds_f4(aaddr);
    float4 a1 = lds_f4(aaddr + 16);
    u64 b0, b1, b2, b3;
    lds_v2u64(b0, b1, baddr);
    lds_v2u64(b2, b3, baddr + 16);
    macro_b(acc, b0, b1, b2, b3, a0, a1);
}

// ---------------- fused kernel ----------------
__global__ __launch_bounds__(THREADS, 2) void logsig_kernel(const float* __restrict__ x,
                                                            float* __restrict__ out) {
    const int b    = blockIdx.x >> 2;
    const int s    = blockIdx.x & 3;
    const int tid  = threadIdx.x;
    const int w    = tid >> 5;
    const int lane = tid & 31;
    const int h    = lane >> 4;        // l-parity within the macro pair
    const int r    = lane & 15;        // tile id within 32x32
    const int i0   = (r & 3) * 8;
    const int j0   = (r >> 2) * 8;

    __shared__ float sbuf[NBUF][CHUNK_R][ROWF];   // 36864 B
    __shared__ int   sflag;

    const float* gseg = x + ((size_t)b * LSEQ + (size_t)s * SEG_ROWS) * DIMV;
    unsigned sbase = (unsigned)__cvta_generic_to_shared(&sbuf[0][0][0]);

    // prologue: prefetch chunks 0,1
    copy_chunk(gseg, sbase + 0 * CHUNK_BYTES, 0, tid); cp_commit();
    copy_chunk(gseg, sbase + 1 * CHUNK_BYTES, 1, tid); cp_commit();

    const bool tailw = (w == 7) && (h == 1);

    u64 acc[32];
#pragma unroll
    for (int i = 0; i < 32; i++) acc[i] = 0ull;

#pragma unroll 1
    for (int c = 0; c < NCHUNK; c++) {
        // boundary b-row for this chunk's last macro (row (c+1)*128 of the segment,
        // which is the next chunk's row 0, or for c==3 the next segment's row 0)
        u64 pb0 = 0, pb1 = 0, pb2 = 0, pb3 = 0;
        const bool have_bnd = tailw && (c < NCHUNK - 1 || s < SEGS - 1);
        if (have_bnd) {
            const float* gb = gseg + (size_t)(c + 1) * CHUNK_R * DIMV + j0;
            float4 t0 = *(const float4*)gb;
            float4 t1 = *(const float4*)(gb + 4);
            pb0 = pk2(t0.x, t0.y); pb1 = pk2(t0.z, t0.w);
            pb2 = pk2(t1.x, t1.y); pb3 = pk2(t1.z, t1.w);
        }

        if (c < NCHUNK - 1) cp_wait<1>(); else cp_wait<0>();
        __syncthreads();

        unsigned buf   = sbase + (unsigned)(c & 1) * CHUNK_BYTES;
        unsigned aaddr = buf + (unsigned)(w * 16 + h) * ROWB + (unsigned)i0 * 4u;
        unsigned baddr = buf + (unsigned)(w * 16 + h + 1) * ROWB + (unsigned)j0 * 4u;

#pragma unroll
        for (int m = 0; m < 7; m++) {
            macro_ab(acc, aaddr, baddr);
            aaddr += 2 * ROWB; baddr += 2 * ROWB;
        }
        // m == 7: b-row crosses the chunk boundary for (w7,h1)
        if (!tailw) {
            macro_ab(acc, aaddr, baddr);
        } else if (have_bnd) {
            float4 a0 = lds_f4(aaddr);
            float4 a1 = lds_f4(aaddr + 16);
            macro_b(acc, pb0, pb1, pb2, pb3, a0, a1);
        }
        // (c==3, s==3, tailw: step l=2047 doesn't exist -> skip)

        __syncthreads();
        if (c + 2 < NCHUNK) { copy_chunk(gseg, buf, c + 2, tid); cp_commit(); }
    }

    // combine the two l-parities: lane r += lane r+16
#pragma unroll
    for (int k = 0; k < 32; k++) {
        u64 o = __shfl_down_sync(0xffffffffu, acc[k], 16);
        if (h == 0) acc[k] = add2(acc[k], o);
    }

    // per-warp partials -> smem (reuse chunk buffers: need 32 KB <= 36.9 KB)
    float* pr = &sbuf[0][0][0];
    if (h == 0) {
#pragma unroll
        for (int ii = 0; ii < 8; ii++) {
#pragma unroll
            for (int jp = 0; jp < 4; jp++) {
                *(u64*)&pr[w * 1024 + (i0 + ii) * 32 + j0 + 2 * jp] = acc[ii * 4 + jp];
            }
        }
    }
    __syncthreads();

    const int e0 = tid * 4;
    {
        float4 sum = make_float4(0.f, 0.f, 0.f, 0.f);
#pragma unroll
        for (int ww = 0; ww < 8; ww++) {
            float4 v = *(const float4*)&pr[ww * 1024 + e0];
            sum.x += v.x; sum.y += v.y; sum.z += v.z; sum.w += v.w;
        }
        *(float4*)&g_part[((size_t)b * SEGS + s) * 1024 + e0] = sum;
    }

    // ---------- last-CTA-per-batch combine (deterministic fixed-order sum) ----------
    __threadfence();
    if (tid == 0) {
        int old = atomicAdd(&g_cnt[b], 1);
        sflag = (old == SEGS - 1);
        if (old == SEGS - 1) g_cnt[b] = 0;   // reset for next graph replay
    }
    __syncthreads();
    if (!sflag) return;

    __threadfence();  // acquire: make all 4 partials visible

    // reuse smem: Cs[1024] + x0s/l1s
    float* Cs  = &sbuf[0][0][0];
    float* x0s = Cs + 1024;
    float* l1s = Cs + 1024 + DIMV;

    {
        float4 tot = make_float4(0.f, 0.f, 0.f, 0.f);
#pragma unroll
        for (int ss = 0; ss < SEGS; ss++) {
            float4 v = *(const float4*)&g_part[((size_t)b * SEGS + ss) * 1024 + e0];
            tot.x += v.x; tot.y += v.y; tot.z += v.z; tot.w += v.w;
        }
        __syncthreads();              // pr reads above are long done; order vs Cs writes
        *(float4*)&Cs[e0] = tot;
    }

    if (tid < DIMV) {
        float x0 = x[(size_t)b * LSEQ * DIMV + tid];
        float xl = x[(size_t)b * LSEQ * DIMV + (size_t)(LSEQ - 1) * DIMV + tid];
        float l1 = xl - x0;
        x0s[tid] = x0;
        l1s[tid] = l1;
        out[(size_t)b * OUTW + tid] = l1;
    }
    __syncthreads();

#pragma unroll
    for (int p = tid; p < NPAIRS; p += THREADS) {
        // closed-form inversion p -> (i, j), i<j, row-major upper triangle
        float f = (63.0f - sqrtf((float)(3969 - 8 * p))) * 0.5f;
        int i = (int)f;
        int base = i * (63 - i) / 2;
        if (base > p) { i--; base = i * (63 - i) / 2; }
        else {
            int nb = (i + 1) * (62 - i) / 2;
            if (nb <= p) { i++; base = nb; }
        }
        int j = i + 1 + (p - base);
        float val = 0.5f * ((Cs[i * 32 + j] - Cs[j * 32 + i])
                            - x0s[i] * l1s[j] + x0s[j] * l1s[i]);
        out[(size_t)b * OUTW + DIMV + p] = val;
    }
}

// ---------------- launch ----------------
extern "C" void kernel_launch(void* const* d_in, const int* in_sizes, int n_in,
                              void* d_out, int out_size) {
    const float* x = (const float*)d_in[0];
    float* out = (float*)d_out;
    const int B = in_sizes[0] / (LSEQ * DIMV);  // 512

    logsig_kernel<<<B * SEGS, THREADS>>>(x, out);
}

// round 6
// speedup vs baseline: 1.8296x; 1.8296x over previous
#include <cuda_runtime.h>
#include <cuda_bf16.h>
#include <cstdint>

typedef unsigned long long u64;

// ---------------- constants ----------------
#define LSEQ     2048
#define DIMV     32
#define SEGS     4
#define SEG_ROWS 512
#define CHUNK_R  128
#define NCHUNK   4
#define NBUF     2
#define THREADS  256
#define NPAIRS   496
#define OUTW     528
#define ROWF     36                        // padded row: 36 floats = 144 B (bank shift 4/row)
#define ROWB     (ROWF * 4)                // 144
#define CHUNK_BYTES (CHUNK_R * ROWB)       // 18432

// partial C scratch: [B][SEGS][32*32] fp32 = 8 MB
__device__ float g_part[512 * SEGS * 1024];

// ---------------- f32x2 helpers ----------------
__device__ __forceinline__ u64 fma2(u64 a, u64 b, u64 c) {
    u64 d;
    asm("fma.rn.f32x2 %0, %1, %2, %3;" : "=l"(d) : "l"(a), "l"(b), "l"(c));
    return d;
}
__device__ __forceinline__ u64 add2(u64 a, u64 b) {
    u64 d;
    asm("add.rn.f32x2 %0, %1, %2;" : "=l"(d) : "l"(a), "l"(b));
    return d;
}
__device__ __forceinline__ u64 splat(float x) {
    u64 r;
    asm("mov.b64 %0, {%1, %1};" : "=l"(r) : "f"(x));
    return r;
}

// ---------------- shared-memory access (32-bit addresses) ----------------
__device__ __forceinline__ void lds_v2u64(u64& b0, u64& b1, unsigned addr) {
    asm volatile("ld.shared.v2.b64 {%0, %1}, [%2];" : "=l"(b0), "=l"(b1) : "r"(addr));
}
__device__ __forceinline__ float4 lds_f4(unsigned addr) {
    float4 v;
    asm volatile("ld.shared.v4.f32 {%0, %1, %2, %3}, [%4];"
                 : "=f"(v.x), "=f"(v.y), "=f"(v.z), "=f"(v.w) : "r"(addr));
    return v;
}

// ---------------- cp.async ----------------
__device__ __forceinline__ void cp_commit() { asm volatile("cp.async.commit_group;"); }
template <int N>
__device__ __forceinline__ void cp_wait() { asm volatile("cp.async.wait_group %0;" ::"n"(N)); }

// copy one 128x32 fp32 chunk (16 KB gmem) into a padded smem buffer (144 B rows)
__device__ __forceinline__ void copy_chunk(const float* __restrict__ gseg,
                                           unsigned sb_addr, int c, int tid) {
    const char* gsrc = (const char*)(gseg + (size_t)c * CHUNK_R * DIMV);
#pragma unroll
    for (int i = 0; i < 4; i++) {
        int p   = tid + i * 256;            // 1024 pieces of 16 B
        int row = p >> 3;
        int sub = p & 7;
        unsigned dst = sb_addr + (unsigned)row * ROWB + (unsigned)sub * 16u;
        const char* src = gsrc + row * 128 + sub * 16;
        asm volatile("cp.async.cg.shared.global [%0], [%1], 16;" ::"r"(dst), "l"(src));
    }
}

// ---------------- macro step: 8x8 outer product (2 l-steps via h split) ----------
__device__ __forceinline__ void macro_b(u64* acc, u64 b0, u64 b1, u64 b2, u64 b3,
                                        float4 a0, float4 a1) {
    float av[8] = {a0.x, a0.y, a0.z, a0.w, a1.x, a1.y, a1.z, a1.w};
#pragma unroll
    for (int ii = 0; ii < 8; ii++) {
        u64 s = splat(av[ii]);
        acc[ii * 4 + 0] = fma2(s, b0, acc[ii * 4 + 0]);
        acc[ii * 4 + 1] = fma2(s, b1, acc[ii * 4 + 1]);
        acc[ii * 4 + 2] = fma2(s, b2, acc[ii * 4 + 2]);
        acc[ii * 4 + 3] = fma2(s, b3, acc[ii * 4 + 3]);
    }
}
__device__ __forceinline__ void macro_ab(u64* acc, unsigned aaddr, unsigned baddr) {
    float4 a0 = lds_f4(aaddr);
    float4 a1 = lds_f4(aaddr + 16);
    u64 b0, b1, b2, b3;
    lds_v2u64(b0, b1, baddr);
    lds_v2u64(b2, b3, baddr + 16);
    macro_b(acc, b0, b1, b2, b3, a0, a1);
}

// ---------------- kernel 1: partial C per (batch, segment) ----------------
__global__ __launch_bounds__(THREADS, 2) void logsig_part_kernel(const float* __restrict__ x) {
    const int b    = blockIdx.x >> 2;
    const int s    = blockIdx.x & 3;
    const int tid  = threadIdx.x;
    const int w    = tid >> 5;
    const int lane = tid & 31;
    const int h    = lane >> 4;        // l-parity within the macro pair
    const int r    = lane & 15;        // tile id within 32x32
    const int i0   = (r & 3) * 8;
    const int j0   = (r >> 2) * 8;

    __shared__ float sbuf[NBUF][CHUNK_R][ROWF];   // 36864 B
    __shared__ float sbnd[NCHUNK][ROWF];          // boundary rows (row 0 of chunk c+1)

    const float* gseg = x + ((size_t)b * LSEQ + (size_t)s * SEG_ROWS) * DIMV;
    unsigned sbase = (unsigned)__cvta_generic_to_shared(&sbuf[0][0][0]);
    unsigned bbase = (unsigned)__cvta_generic_to_shared(&sbnd[0][0]);

    // prologue: prefetch chunks 0,1
    copy_chunk(gseg, sbase + 0 * CHUNK_BYTES, 0, tid); cp_commit();
    copy_chunk(gseg, sbase + 1 * CHUNK_BYTES, 1, tid); cp_commit();

    // boundary rows: global rows (c+1)*128 of this segment, c = 0..3.
    // For s==3, c==3 that row (l = 2048) doesn't exist -> 0 (contributes nothing).
    if (tid < NCHUNK * DIMV) {
        int rr  = tid >> 5;            // 0..3
        int col = tid & 31;
        int g   = s * SEG_ROWS + (rr + 1) * CHUNK_R;   // global row index
        float v = 0.0f;
        if (g < LSEQ) v = x[((size_t)b * LSEQ + g) * DIMV + col];
        sbnd[rr][col] = v;
    }

    const bool tailw = (w == 7) && (h == 1);

    u64 acc[32];
#pragma unroll
    for (int i = 0; i < 32; i++) acc[i] = 0ull;

#pragma unroll 1
    for (int c = 0; c < NCHUNK; c++) {
        if (c < NCHUNK - 1) cp_wait<1>(); else cp_wait<0>();
        __syncthreads();   // also makes sbnd visible (written before first barrier)

        unsigned buf   = sbase + (unsigned)(c & 1) * CHUNK_BYTES;
        unsigned aaddr = buf + (unsigned)(w * 16 + h) * ROWB + (unsigned)i0 * 4u;
        unsigned baddr = buf + (unsigned)(w * 16 + h + 1) * ROWB + (unsigned)j0 * 4u;

#pragma unroll
        for (int m = 0; m < 7; m++) {
            macro_ab(acc, aaddr, baddr);
            aaddr += 2 * ROWB; baddr += 2 * ROWB;
        }
        // m == 7: for (w7,h1) the b-row is row 0 of the next chunk -> staged in sbnd[c]
        unsigned bl = tailw ? (bbase + (unsigned)c * ROWB + (unsigned)j0 * 4u) : baddr;
        macro_ab(acc, aaddr, bl);

        __syncthreads();
        if (c + 2 < NCHUNK) { copy_chunk(gseg, buf, c + 2, tid); cp_commit(); }
    }

    // combine the two l-parities: lane r += lane r+16
#pragma unroll
    for (int k = 0; k < 32; k++) {
        u64 o = __shfl_down_sync(0xffffffffu, acc[k], 16);
        if (h == 0) acc[k] = add2(acc[k], o);
    }

    // per-warp partials -> smem (reuse chunk buffers; 32 KB <= 36.9 KB)
    float* pr = &sbuf[0][0][0];
    if (h == 0) {
#pragma unroll
        for (int ii = 0; ii < 8; ii++) {
#pragma unroll
            for (int jp = 0; jp < 4; jp++) {
                *(u64*)&pr[w * 1024 + (i0 + ii) * 32 + j0 + 2 * jp] = acc[ii * 4 + jp];
            }
        }
    }
    __syncthreads();

    const int e0 = tid * 4;
    float4 sum = make_float4(0.f, 0.f, 0.f, 0.f);
#pragma unroll
    for (int ww = 0; ww < 8; ww++) {
        float4 v = *(const float4*)&pr[ww * 1024 + e0];
        sum.x += v.x; sum.y += v.y; sum.z += v.z; sum.w += v.w;
    }
    *(float4*)&g_part[((size_t)b * SEGS + s) * 1024 + e0] = sum;
}

// ---------------- kernel 2: combine + outputs ----------------
__global__ __launch_bounds__(THREADS) void logsig_final_kernel(const float* __restrict__ x,
                                                               float* __restrict__ out) {
    const int b   = blockIdx.x;
    const int tid = threadIdx.x;

    __shared__ float Cs[1024];
    __shared__ float x0s[DIMV];
    __shared__ float l1s[DIMV];

    const int e0 = tid * 4;
    float4 sum = make_float4(0.f, 0.f, 0.f, 0.f);
#pragma unroll
    for (int s = 0; s < SEGS; s++) {
        float4 v = *(const float4*)&g_part[((size_t)b * SEGS + s) * 1024 + e0];
        sum.x += v.x; sum.y += v.y; sum.z += v.z; sum.w += v.w;
    }
    *(float4*)&Cs[e0] = sum;

    if (tid < DIMV) {
        float x0 = x[(size_t)b * LSEQ * DIMV + tid];
        float xl = x[(size_t)b * LSEQ * DIMV + (size_t)(LSEQ - 1) * DIMV + tid];
        float l1 = xl - x0;
        x0s[tid] = x0;
        l1s[tid] = l1;
        out[(size_t)b * OUTW + tid] = l1;
    }
    __syncthreads();

#pragma unroll
    for (int p = tid; p < NPAIRS; p += THREADS) {
        // closed-form inversion p -> (i, j), i<j, row-major upper triangle
        float f = (63.0f - sqrtf((float)(3969 - 8 * p))) * 0.5f;
        int i = (int)f;
        int base = i * (63 - i) / 2;
        if (base > p) { i--; base = i * (63 - i) / 2; }
        else {
            int nb = (i + 1) * (62 - i) / 2;
            if (nb <= p) { i++; base = nb; }
        }
        int j = i + 1 + (p - base);
        float val = 0.5f * ((Cs[i * 32 + j] - Cs[j * 32 + i])
                            - x0s[i] * l1s[j] + x0s[j] * l1s[i]);
        out[(size_t)b * OUTW + DIMV + p] = val;
    }
}

// ---------------- launch ----------------
extern "C" void kernel_launch(void* const* d_in, const int* in_sizes, int n_in,
                              void* d_out, int out_size) {
    const float* x = (const float*)d_in[0];
    float* out = (float*)d_out;
    const int B = in_sizes[0] / (LSEQ * DIMV);  // 512

    logsig_part_kernel<<<B * SEGS, THREADS>>>(x);
    logsig_final_kernel<<<B, THREADS>>>(x, out);
}

// round 7
// speedup vs baseline: 1.8397x; 1.0055x over previous
#include <cuda_runtime.h>
#include <cuda_bf16.h>
#include <cstdint>

typedef unsigned long long u64;

// ---------------- constants ----------------
#define LSEQ     2048
#define DIMV     32
#define SEGS     4
#define SEG_ROWS 512
#define CHUNK_R  128
#define NCHUNK   4
#define NBUF     2
#define THREADS  256
#define NPAIRS   496
#define OUTW     528
#define ROWF     36                        // padded row: 36 floats = 144 B (bank shift 4/row)
#define ROWB     (ROWF * 4)                // 144
#define CHUNK_BYTES (CHUNK_R * ROWB)       // 18432

// partial C scratch: [B][SEGS][32*32] fp32 = 8 MB
__device__ float g_part[512 * SEGS * 1024];

// ---------------- f32x2 helpers ----------------
__device__ __forceinline__ u64 fma2(u64 a, u64 b, u64 c) {
    u64 d;
    asm("fma.rn.f32x2 %0, %1, %2, %3;" : "=l"(d) : "l"(a), "l"(b), "l"(c));
    return d;
}
__device__ __forceinline__ u64 add2(u64 a, u64 b) {
    u64 d;
    asm("add.rn.f32x2 %0, %1, %2;" : "=l"(d) : "l"(a), "l"(b));
    return d;
}
__device__ __forceinline__ u64 splat(float x) {
    u64 r;
    asm("mov.b64 %0, {%1, %1};" : "=l"(r) : "f"(x));
    return r;
}

// ---------------- shared-memory access (32-bit addresses) ----------------
__device__ __forceinline__ void lds_v2u64(u64& b0, u64& b1, unsigned addr) {
    asm volatile("ld.shared.v2.b64 {%0, %1}, [%2];" : "=l"(b0), "=l"(b1) : "r"(addr));
}
__device__ __forceinline__ float4 lds_f4(unsigned addr) {
    float4 v;
    asm volatile("ld.shared.v4.f32 {%0, %1, %2, %3}, [%4];"
                 : "=f"(v.x), "=f"(v.y), "=f"(v.z), "=f"(v.w) : "r"(addr));
    return v;
}

// ---------------- cp.async ----------------
__device__ __forceinline__ void cp_commit() { asm volatile("cp.async.commit_group;"); }
template <int N>
__device__ __forceinline__ void cp_wait() { asm volatile("cp.async.wait_group %0;" ::"n"(N)); }

// copy one 128x32 fp32 chunk (16 KB gmem) into a padded smem buffer (144 B rows)
__device__ __forceinline__ void copy_chunk(const float* __restrict__ gseg,
                                           unsigned sb_addr, int c, int tid) {
    const char* gsrc = (const char*)(gseg + (size_t)c * CHUNK_R * DIMV);
#pragma unroll
    for (int i = 0; i < 4; i++) {
        int p   = tid + i * 256;            // 1024 pieces of 16 B
        int row = p >> 3;
        int sub = p & 7;
        unsigned dst = sb_addr + (unsigned)row * ROWB + (unsigned)sub * 16u;
        const char* src = gsrc + row * 128 + sub * 16;
        asm volatile("cp.async.cg.shared.global [%0], [%1], 16;" ::"r"(dst), "l"(src));
    }
}

// ---------------- macro step: 8x8 outer product (2 l-steps via h split) ----------
__device__ __forceinline__ void macro_b(u64* acc, u64 b0, u64 b1, u64 b2, u64 b3,
                                        float4 a0, float4 a1) {
    float av[8] = {a0.x, a0.y, a0.z, a0.w, a1.x, a1.y, a1.z, a1.w};
#pragma unroll
    for (int ii = 0; ii < 8; ii++) {
        u64 s = splat(av[ii]);
        acc[ii * 4 + 0] = fma2(s, b0, acc[ii * 4 + 0]);
        acc[ii * 4 + 1] = fma2(s, b1, acc[ii * 4 + 1]);
        acc[ii * 4 + 2] = fma2(s, b2, acc[ii * 4 + 2]);
        acc[ii * 4 + 3] = fma2(s, b3, acc[ii * 4 + 3]);
    }
}
__device__ __forceinline__ void macro_ab(u64* acc, unsigned aaddr, unsigned baddr) {
    float4 a0 = lds_f4(aaddr);
    float4 a1 = lds_f4(aaddr + 16);
    u64 b0, b1, b2, b3;
    lds_v2u64(b0, b1, baddr);
    lds_v2u64(b2, b3, baddr + 16);
    macro_b(acc, b0, b1, b2, b3, a0, a1);
}

// ---------------- kernel 1: partial C per (batch, segment) ----------------
__global__ __launch_bounds__(THREADS, 2) void logsig_part_kernel(const float* __restrict__ x) {
    const int b    = blockIdx.x >> 2;
    const int s    = blockIdx.x & 3;
    const int tid  = threadIdx.x;
    const int w    = tid >> 5;
    const int lane = tid & 31;
    const int h    = lane >> 4;        // l-parity within the macro pair
    const int r    = lane & 15;        // tile id within 32x32
    const int i0   = (r & 3) * 8;
    const int j0   = (r >> 2) * 8;

    __shared__ float sbuf[NBUF][CHUNK_R][ROWF];   // 36864 B
    __shared__ float sbnd[NCHUNK][ROWF];          // boundary rows (row 0 of chunk c+1)

    const float* gseg = x + ((size_t)b * LSEQ + (size_t)s * SEG_ROWS) * DIMV;
    unsigned sbase = (unsigned)__cvta_generic_to_shared(&sbuf[0][0][0]);
    unsigned bbase = (unsigned)__cvta_generic_to_shared(&sbnd[0][0]);

    // prologue: prefetch chunks 0,1
    copy_chunk(gseg, sbase + 0 * CHUNK_BYTES, 0, tid); cp_commit();
    copy_chunk(gseg, sbase + 1 * CHUNK_BYTES, 1, tid); cp_commit();

    // boundary rows: global rows (c+1)*128 of this segment, c = 0..3.
    // For s==3, c==3 that row (l = 2048) doesn't exist -> 0 (contributes nothing).
    if (tid < NCHUNK * DIMV) {
        int rr  = tid >> 5;            // 0..3
        int col = tid & 31;
        int g   = s * SEG_ROWS + (rr + 1) * CHUNK_R;   // global row index
        float v = 0.0f;
        if (g < LSEQ) v = x[((size_t)b * LSEQ + g) * DIMV + col];
        sbnd[rr][col] = v;
    }

    const bool tailw = (w == 7) && (h == 1);

    u64 acc[32];
#pragma unroll
    for (int i = 0; i < 32; i++) acc[i] = 0ull;

#pragma unroll 1
    for (int c = 0; c < NCHUNK; c++) {
        if (c < NCHUNK - 1) cp_wait<1>(); else cp_wait<0>();
        __syncthreads();   // also makes sbnd visible (written before first barrier)

        unsigned buf   = sbase + (unsigned)(c & 1) * CHUNK_BYTES;
        unsigned aaddr = buf + (unsigned)(w * 16 + h) * ROWB + (unsigned)i0 * 4u;
        unsigned baddr = buf + (unsigned)(w * 16 + h + 1) * ROWB + (unsigned)j0 * 4u;

#pragma unroll
        for (int m = 0; m < 7; m++) {
            macro_ab(acc, aaddr, baddr);
            aaddr += 2 * ROWB; baddr += 2 * ROWB;
        }
        // m == 7: for (w7,h1) the b-row is row 0 of the next chunk -> staged in sbnd[c]
        unsigned bl = tailw ? (bbase + (unsigned)c * ROWB + (unsigned)j0 * 4u) : baddr;
        macro_ab(acc, aaddr, bl);

        __syncthreads();
        if (c + 2 < NCHUNK) { copy_chunk(gseg, buf, c + 2, tid); cp_commit(); }
    }

    // combine the two l-parities: lane r += lane r+16
#pragma unroll
    for (int k = 0; k < 32; k++) {
        u64 o = __shfl_down_sync(0xffffffffu, acc[k], 16);
        if (h == 0) acc[k] = add2(acc[k], o);
    }

    // per-warp partials -> smem (reuse chunk buffers; 32 KB <= 36.9 KB)
    float* pr = &sbuf[0][0][0];
    if (h == 0) {
#pragma unroll
        for (int ii = 0; ii < 8; ii++) {
#pragma unroll
            for (int jp = 0; jp < 4; jp++) {
                *(u64*)&pr[w * 1024 + (i0 + ii) * 32 + j0 + 2 * jp] = acc[ii * 4 + jp];
            }
        }
    }
    __syncthreads();

    const int e0 = tid * 4;
    float4 sum = make_float4(0.f, 0.f, 0.f, 0.f);
#pragma unroll
    for (int ww = 0; ww < 8; ww++) {
        float4 v = *(const float4*)&pr[ww * 1024 + e0];
        sum.x += v.x; sum.y += v.y; sum.z += v.z; sum.w += v.w;
    }
    *(float4*)&g_part[((size_t)b * SEGS + s) * 1024 + e0] = sum;
}

// ---------------- kernel 2: combine + outputs ----------------
__global__ __launch_bounds__(THREADS) void logsig_final_kernel(const float* __restrict__ x,
                                                               float* __restrict__ out) {
    const int b   = blockIdx.x;
    const int tid = threadIdx.x;

    __shared__ float Cs[1024];
    __shared__ float x0s[DIMV];
    __shared__ float l1s[DIMV];

    const int e0 = tid * 4;
    float4 sum = make_float4(0.f, 0.f, 0.f, 0.f);
#pragma unroll
    for (int s = 0; s < SEGS; s++) {
        float4 v = *(const float4*)&g_part[((size_t)b * SEGS + s) * 1024 + e0];
        sum.x += v.x; sum.y += v.y; sum.z += v.z; sum.w += v.w;
    }
    *(float4*)&Cs[e0] = sum;

    if (tid < DIMV) {
        float x0 = x[(size_t)b * LSEQ * DIMV + tid];
        float xl = x[(size_t)b * LSEQ * DIMV + (size_t)(LSEQ - 1) * DIMV + tid];
        float l1 = xl - x0;
        x0s[tid] = x0;
        l1s[tid] = l1;
        out[(size_t)b * OUTW + tid] = l1;
    }
    __syncthreads();

#pragma unroll
    for (int p = tid; p < NPAIRS; p += THREADS) {
        // closed-form inversion p -> (i, j), i<j, row-major upper triangle
        float f = (63.0f - sqrtf((float)(3969 - 8 * p))) * 0.5f;
        int i = (int)f;
        int base = i * (63 - i) / 2;
        if (base > p) { i--; base = i * (63 - i) / 2; }
        else {
            int nb = (i + 1) * (62 - i) / 2;
            if (nb <= p) { i++; base = nb; }
        }
        int j = i + 1 + (p - base);
        float val = 0.5f * ((Cs[i * 32 + j] - Cs[j * 32 + i])
                            - x0s[i] * l1s[j] + x0s[j] * l1s[i]);
        out[(size_t)b * OUTW + DIMV + p] = val;
    }
}

// ---------------- launch ----------------
extern "C" void kernel_launch(void* const* d_in, const int* in_sizes, int n_in,
                              void* d_out, int out_size) {
    const float* x = (const float*)d_in[0];
    float* out = (float*)d_out;
    const int B = in_sizes[0] / (LSEQ * DIMV);  // 512

    logsig_part_kernel<<<B * SEGS, THREADS>>>(x);
    logsig_final_kernel<<<B, THREADS>>>(x, out);
}

// round 9
// speedup vs baseline: 1.8899x; 1.0273x over previous
#include <cuda_runtime.h>
#include <cuda_bf16.h>
#include <cstdint>

typedef unsigned long long u64;
typedef unsigned int u32;

#define LSEQ 2048
#define DIMV 32
#define CHK 64
#define NCH 32
#define THREADS 256
#define NPAIRS 496
#define OUTW 528

#define AOFF 0
#define BOFF 8192
#define RAW0 16384
#define RAWROW 144
#define RAWSZ (65 * RAWROW)            // 9360
#define SMEMSZ (RAW0 + 2 * RAWSZ)      // 35104

__device__ __forceinline__ u32 smem_u32(const void* p) {
    u32 a;
    asm("{ .reg .u64 t; cvta.to.shared.u64 t, %1; cvt.u32.u64 %0, t; }" : "=r"(a) : "l"(p));
    return a;
}
__device__ __forceinline__ u32 cvtpack(float lo, float hi) {   // low half = lo
    u32 r;
    asm("cvt.rn.bf16x2.f32 %0, %1, %2;" : "=r"(r) : "f"(hi), "f"(lo));
    return r;
}
__device__ __forceinline__ float lds_f32(u32 a) {
    float v;
    asm volatile("ld.shared.f32 %0, [%1];" : "=f"(v) : "r"(a));
    return v;
}
__device__ __forceinline__ void sts128(u32 a, u32 x0, u32 x1, u32 x2, u32 x3) {
    asm volatile("st.shared.v4.b32 [%0], {%1,%2,%3,%4};"
                 ::"r"(a), "r"(x0), "r"(x1), "r"(x2), "r"(x3));
}
__device__ __forceinline__ void cp16(u32 dst, const void* src) {
    asm volatile("cp.async.cg.shared.global [%0], [%1], 16;" ::"r"(dst), "l"(src));
}
__device__ __forceinline__ void ldsm4(u32 addr, u32* r) {
    asm volatile("ldmatrix.sync.aligned.m8n8.x4.shared.b16 {%0,%1,%2,%3}, [%4];"
                 : "=r"(r[0]), "=r"(r[1]), "=r"(r[2]), "=r"(r[3]) : "r"(addr));
}
__device__ __forceinline__ void mma16816(float* d, const u32* a, u32 b0, u32 b1) {
    asm volatile(
        "mma.sync.aligned.m16n8k16.row.col.f32.bf16.bf16.f32 "
        "{%0,%1,%2,%3}, {%4,%5,%6,%7}, {%8,%9}, {%0,%1,%2,%3};"
        : "+f"(d[0]), "+f"(d[1]), "+f"(d[2]), "+f"(d[3])
        : "r"(a[0]), "r"(a[1]), "r"(a[2]), "r"(a[3]), "r"(b0), "r"(b1));
}

__global__ __launch_bounds__(THREADS, 2) void logsig_mma(const float* __restrict__ x,
                                                         float* __restrict__ out) {
    __shared__ __align__(128) char smem[SMEMSZ];
    __shared__ float x0s[DIMV], l1s[DIMV];

    const int b = blockIdx.x, tid = threadIdx.x, w = tid >> 5, lane = tid & 31;
    const int mh = w & 1, nh = (w >> 1) & 1, kh = w >> 2;   // warp = (m-half, n-half, k-half)
    const float* gx = x + (size_t)b * LSEQ * DIMV;
    const u32 sbase = smem_u32(smem);

    auto prefetch = [&](int c) {
        u32 dbase = sbase + RAW0 + (u32)(c & 1) * RAWSZ;
        const char* src = (const char*)(gx + (size_t)c * CHK * DIMV);
        int ng = (c == NCH - 1) ? 512 : 520;                 // 16B groups (65 rows x 8)
#pragma unroll 1
        for (int g = tid; g < ng; g += THREADS)
            cp16(dbase + (u32)(g >> 3) * RAWROW + (u32)(g & 7) * 16u, src + (size_t)g * 16);
        if (c == NCH - 1 && tid < DIMV)                      // x[2048] := 0
            asm volatile("st.shared.f32 [%0], %1;"
                         ::"r"(dbase + 64u * RAWROW + (u32)tid * 4u), "f"(0.f));
        asm volatile("cp.async.commit_group;");
    };
    prefetch(0);
    prefetch(1);

    // conversion mapping: thread (w, lane) -> dim d = lane, step block = 8*w
    const u32 rawrd = (u32)(8 * w) * RAWROW + (u32)lane * 4u;
    const u32 ust = (u32)((w ^ (lane & 7)) << 4);            // swizzled 16B unit
    const u32 stA = sbase + AOFF + (u32)lane * 128u + ust;
    const u32 stB = sbase + BOFF + (u32)lane * 128u + ust;

    float acc[8][4];
#pragma unroll
    for (int i = 0; i < 8; i++)
#pragma unroll
        for (int r = 0; r < 4; r++) acc[i][r] = 0.f;

#pragma unroll 1
    for (int c = 0; c < NCH; c++) {
        if (c < NCH - 1) asm volatile("cp.async.wait_group 1;");
        else             asm volatile("cp.async.wait_group 0;");
        __syncthreads();

        // ---- convert: 9 raw f32 -> bf16 hi/lo, 4x STS.128 ----
        {
            u32 rbase = sbase + RAW0 + (u32)(c & 1) * RAWSZ + rawrd;
            float v[9], res[9];
            u32 h2[9];
#pragma unroll
            for (int j = 0; j < 9; j++) v[j] = lds_f32(rbase + (u32)j * RAWROW);
#pragma unroll
            for (int j = 0; j < 9; j++) {
                h2[j] = cvtpack(v[j], v[j]);                 // both halves = bf16(v)
                res[j] = v[j] - __uint_as_float(h2[j] & 0xFFFF0000u);
            }
            u32 ah[4], al[4], bh[4], bl[4];
#pragma unroll
            for (int i = 0; i < 4; i++) {
                ah[i] = __byte_perm(h2[2 * i], h2[2 * i + 1], 0x7632);
                al[i] = cvtpack(res[2 * i], res[2 * i + 1]);
                bh[i] = __byte_perm(h2[2 * i + 1], h2[2 * i + 2], 0x7632);
                bl[i] = cvtpack(res[2 * i + 1], res[2 * i + 2]);
            }
            sts128(stA, ah[0], ah[1], ah[2], ah[3]);         // hi rows d
            sts128(stA + 4096u, al[0], al[1], al[2], al[3]); // lo rows d+32
            sts128(stB, bh[0], bh[1], bh[2], bh[3]);
            sts128(stB + 4096u, bl[0], bl[1], bl[2], bl[3]);
        }
        __syncthreads();

        // ---- ldmatrix + mma: this warp's k-half (2 k16 blocks) ----
        const int rla = lane & 15, khl = lane >> 4;
#pragma unroll
        for (int qi = 0; qi < 2; qi++) {
            const u32 u = (u32)((kh * 2 + qi) * 2 + khl);
            u32 afr[2][4], bfr[2][4];
#pragma unroll
            for (int tm = 0; tm < 2; tm++) {
                u32 row = (u32)(mh * 32 + tm * 16 + rla);
                ldsm4(sbase + AOFF + row * 128u + ((u ^ (row & 7u)) << 4), afr[tm]);
            }
#pragma unroll
            for (int tn = 0; tn < 2; tn++) {
                u32 row = (u32)(nh * 32 + tn * 16 + rla);
                ldsm4(sbase + BOFF + row * 128u + ((u ^ (row & 7u)) << 4), bfr[tn]);
            }
#pragma unroll
            for (int tm = 0; tm < 2; tm++)
#pragma unroll
                for (int tn = 0; tn < 2; tn++) {
                    mma16816(acc[tm * 4 + tn * 2 + 0], afr[tm], bfr[tn][0], bfr[tn][2]);
                    mma16816(acc[tm * 4 + tn * 2 + 1], afr[tm], bfr[tn][1], bfr[tn][3]);
                }
        }
        if (c + 2 < NCH) prefetch(c + 2);
    }

    __syncthreads();
    // ---- k-half reduction into smem C[64][66] ----
    float* C = (float*)smem;
    if (kh == 0) {
#pragma unroll
        for (int t = 0; t < 8; t++) {
            int tm = t >> 2, tn8 = t & 3;
#pragma unroll
            for (int r = 0; r < 4; r++) {
                int m = mh * 32 + tm * 16 + (lane >> 2) + (r >> 1) * 8;
                int n = nh * 32 + tn8 * 8 + (lane & 3) * 2 + (r & 1);
                C[m * 66 + n] = acc[t][r];
            }
        }
    }
    __syncthreads();
    if (kh == 1) {
#pragma unroll
        for (int t = 0; t < 8; t++) {
            int tm = t >> 2, tn8 = t & 3;
#pragma unroll
            for (int r = 0; r < 4; r++) {
                int m = mh * 32 + tm * 16 + (lane >> 2) + (r >> 1) * 8;
                int n = nh * 32 + tn8 * 8 + (lane & 3) * 2 + (r & 1);
                C[m * 66 + n] += acc[t][r];
            }
        }
    }
    if (tid < DIMV) {
        float x0 = gx[tid];
        float l1 = gx[(size_t)(LSEQ - 1) * DIMV + tid] - x0;
        x0s[tid] = x0;
        l1s[tid] = l1;
        out[(size_t)b * OUTW + tid] = l1;                    // level1
    }
    __syncthreads();

    // ---- areas: combine hi/lo blocks, antisymmetrize, correct, emit ----
#pragma unroll 1
    for (int p = tid; p < NPAIRS; p += THREADS) {
        float f = (63.0f - sqrtf((float)(3969 - 8 * p))) * 0.5f;
        int i = (int)f;
        int base = i * (63 - i) / 2;
        if (base > p) { i--; base = i * (63 - i) / 2; }
        else { int nb = (i + 1) * (62 - i) / 2; if (nb <= p) { i++; base = nb; } }
        int j = i + 1 + (p - base);
        float Cij = C[i * 66 + j] + C[i * 66 + j + 32]
                  + C[(i + 32) * 66 + j] + C[(i + 32) * 66 + j + 32];
        float Cji = C[j * 66 + i] + C[j * 66 + i + 32]
                  + C[(j + 32) * 66 + i] + C[(j + 32) * 66 + i + 32];
        out[(size_t)b * OUTW + DIMV + p] =
            0.5f * ((Cij - Cji) - x0s[i] * l1s[j] + x0s[j] * l1s[i]);
    }
}

extern "C" void kernel_launch(void* const* d_in, const int* in_sizes, int n_in,
                              void* d_out, int out_size) {
    const float* x = (const float*)d_in[0];
    float* out = (float*)d_out;
    const int B = in_sizes[0] / (LSEQ * DIMV);   // 512
    logsig_mma<<<B, THREADS>>>(x, out);
}

// round 10
// speedup vs baseline: 2.2054x; 1.1670x over previous
#include <cuda_runtime.h>
#include <cuda_bf16.h>
#include <cstdint>

typedef unsigned long long u64;
typedef unsigned int u32;

#define LSEQ 2048
#define DIMV 32
#define CHK 64
#define NCH 32
#define THREADS 256
#define NPAIRS 496
#define OUTW 528

#define STAGE 16384                 // A tile (8KB) + B tile (8KB)
#define BOFF 8192
#define SMEMSZ (2 * STAGE)          // 32768

__device__ __forceinline__ u32 smem_u32(const void* p) {
    u32 a;
    asm("{ .reg .u64 t; cvta.to.shared.u64 t, %1; cvt.u32.u64 %0, t; }" : "=r"(a) : "l"(p));
    return a;
}
__device__ __forceinline__ u32 cvtpack(float lo, float hi) {   // low half = lo
    u32 r;
    asm("cvt.rn.bf16x2.f32 %0, %1, %2;" : "=r"(r) : "f"(hi), "f"(lo));
    return r;
}
__device__ __forceinline__ void sts128(u32 a, u32 x0, u32 x1, u32 x2, u32 x3) {
    asm volatile("st.shared.v4.b32 [%0], {%1,%2,%3,%4};"
                 ::"r"(a), "r"(x0), "r"(x1), "r"(x2), "r"(x3));
}
__device__ __forceinline__ void ldsm4(u32 addr, u32* r) {
    asm volatile("ldmatrix.sync.aligned.m8n8.x4.shared.b16 {%0,%1,%2,%3}, [%4];"
                 : "=r"(r[0]), "=r"(r[1]), "=r"(r[2]), "=r"(r[3]) : "r"(addr));
}
__device__ __forceinline__ void mma16816(float* d, const u32* a, u32 b0, u32 b1) {
    asm volatile(
        "mma.sync.aligned.m16n8k16.row.col.f32.bf16.bf16.f32 "
        "{%0,%1,%2,%3}, {%4,%5,%6,%7}, {%8,%9}, {%0,%1,%2,%3};"
        : "+f"(d[0]), "+f"(d[1]), "+f"(d[2]), "+f"(d[3])
        : "r"(a[0]), "r"(a[1]), "r"(a[2]), "r"(a[3]), "r"(b0), "r"(b1));
}

__global__ __launch_bounds__(THREADS, 3) void logsig_mma(const float* __restrict__ x,
                                                         float* __restrict__ out) {
    __shared__ __align__(128) char smem[SMEMSZ];
    __shared__ float x0s[DIMV], l1s[DIMV];

    const int b = blockIdx.x, tid = threadIdx.x, w = tid >> 5, lane = tid & 31;
    const int mh = w & 1, nh = (w >> 1) & 1, kh = w >> 2;   // warp = (m-half, n-half, k-half)
    const float* gx = x + (size_t)b * LSEQ * DIMV;
    const u32 sbase = smem_u32(smem);

    // direct-LDG chunk load: thread (w,lane) -> dim=lane, rows 8w..8w+8 of the chunk
    auto load9 = [&](float* v, int c) {
        const float* p = gx + (size_t)(c * CHK + 8 * w) * DIMV + lane;
#pragma unroll
        for (int j = 0; j < 9; j++) {
            bool ok = (c * CHK + 8 * w + j) < LSEQ;          // only row 2048 fails
            v[j] = ok ? __ldg(p + j * DIMV) : 0.0f;
        }
    };

    // STS bases (swizzled 16B units; unit index = w within a 128B row)
    const u32 ust = (u32)((w ^ (lane & 7)) << 4);
    const u32 stA = sbase + (u32)lane * 128u + ust;

    float acc[8][4];
#pragma unroll
    for (int i = 0; i < 8; i++)
#pragma unroll
        for (int r = 0; r < 4; r++) acc[i][r] = 0.f;

    float vc[9], vn[9];
    load9(vc, 0);

#pragma unroll 2
    for (int c = 0; c < NCH; c++) {
        const u32 buf = (u32)(c & 1) * STAGE;

        // ---- convert: 9 f32 -> bf16 hi/lo, 4x STS.128 into buf ----
        {
            float res[9];
            u32 h2[9];
#pragma unroll
            for (int j = 0; j < 9; j++) {
                h2[j] = cvtpack(vc[j], vc[j]);               // both halves = bf16(v)
                res[j] = vc[j] - __uint_as_float(h2[j] & 0xFFFF0000u);
            }
            u32 ah[4], al[4], bh[4], bl[4];
#pragma unroll
            for (int i = 0; i < 4; i++) {
                ah[i] = __byte_perm(h2[2 * i], h2[2 * i + 1], 0x7632);
                al[i] = cvtpack(res[2 * i], res[2 * i + 1]);
                bh[i] = __byte_perm(h2[2 * i + 1], h2[2 * i + 2], 0x7632);
                bl[i] = cvtpack(res[2 * i + 1], res[2 * i + 2]);
            }
            sts128(stA + buf, ah[0], ah[1], ah[2], ah[3]);            // A hi (row d)
            sts128(stA + buf + 4096u, al[0], al[1], al[2], al[3]);    // A lo (row d+32)
            sts128(stA + buf + BOFF, bh[0], bh[1], bh[2], bh[3]);     // B hi
            sts128(stA + buf + BOFF + 4096u, bl[0], bl[1], bl[2], bl[3]);
        }

        if (c + 1 < NCH) load9(vn, c + 1);    // prefetch next chunk (covered by mma phase)

        __syncthreads();                      // STS(c) visible; also fences ldsm(c-1) vs STS(c+1)

        // ---- ldmatrix + mma: this warp's k-half (2 k16 blocks) ----
        const int rla = lane & 15, khl = lane >> 4;
#pragma unroll
        for (int qi = 0; qi < 2; qi++) {
            const u32 u = (u32)((kh * 2 + qi) * 2 + khl);
            u32 afr[2][4], bfr[2][4];
#pragma unroll
            for (int tm = 0; tm < 2; tm++) {
                u32 row = (u32)(mh * 32 + tm * 16 + rla);
                ldsm4(sbase + buf + row * 128u + ((u ^ (row & 7u)) << 4), afr[tm]);
            }
#pragma unroll
            for (int tn = 0; tn < 2; tn++) {
                u32 row = (u32)(nh * 32 + tn * 16 + rla);
                ldsm4(sbase + buf + BOFF + row * 128u + ((u ^ (row & 7u)) << 4), bfr[tn]);
            }
#pragma unroll
            for (int tm = 0; tm < 2; tm++)
#pragma unroll
                for (int tn = 0; tn < 2; tn++) {
                    mma16816(acc[tm * 4 + tn * 2 + 0], afr[tm], bfr[tn][0], bfr[tn][2]);
                    mma16816(acc[tm * 4 + tn * 2 + 1], afr[tm], bfr[tn][1], bfr[tn][3]);
                }
        }
#pragma unroll
        for (int j = 0; j < 9; j++) vc[j] = vn[j];
    }

    __syncthreads();
    // ---- k-half reduction into smem C[64][66] (reuses tile region) ----
    float* C = (float*)smem;
    if (kh == 0) {
#pragma unroll
        for (int t = 0; t < 8; t++) {
            int tm = t >> 2, tn8 = t & 3;
#pragma unroll
            for (int r = 0; r < 4; r++) {
                int m = mh * 32 + tm * 16 + (lane >> 2) + (r >> 1) * 8;
                int n = nh * 32 + tn8 * 8 + (lane & 3) * 2 + (r & 1);
                C[m * 66 + n] = acc[t][r];
            }
        }
    }
    __syncthreads();
    if (kh == 1) {
#pragma unroll
        for (int t = 0; t < 8; t++) {
            int tm = t >> 2, tn8 = t & 3;
#pragma unroll
            for (int r = 0; r < 4; r++) {
                int m = mh * 32 + tm * 16 + (lane >> 2) + (r >> 1) * 8;
                int n = nh * 32 + tn8 * 8 + (lane & 3) * 2 + (r & 1);
                C[m * 66 + n] += acc[t][r];
            }
        }
    }
    if (tid < DIMV) {
        float x0 = gx[tid];
        float l1 = gx[(size_t)(LSEQ - 1) * DIMV + tid] - x0;
        x0s[tid] = x0;
        l1s[tid] = l1;
        out[(size_t)b * OUTW + tid] = l1;                    // level1
    }
    __syncthreads();

    // ---- areas: combine hi/lo blocks, antisymmetrize, correct, emit ----
#pragma unroll 1
    for (int p = tid; p < NPAIRS; p += THREADS) {
        float f = (63.0f - sqrtf((float)(3969 - 8 * p))) * 0.5f;
        int i = (int)f;
        int base = i * (63 - i) / 2;
        if (base > p) { i--; base = i * (63 - i) / 2; }
        else { int nb = (i + 1) * (62 - i) / 2; if (nb <= p) { i++; base = nb; } }
        int j = i + 1 + (p - base);
        float Cij = C[i * 66 + j] + C[i * 66 + j + 32]
                  + C[(i + 32) * 66 + j] + C[(i + 32) * 66 + j + 32];
        float Cji = C[j * 66 + i] + C[j * 66 + i + 32]
                  + C[(j + 32) * 66 + i] + C[(j + 32) * 66 + i + 32];
        out[(size_t)b * OUTW + DIMV + p] =
            0.5f * ((Cij - Cji) - x0s[i] * l1s[j] + x0s[j] * l1s[i]);
    }
}

extern "C" void kernel_launch(void* const* d_in, const int* in_sizes, int n_in,
                              void* d_out, int out_size) {
    const float* x = (const float*)d_in[0];
    float* out = (float*)d_out;
    const int B = in_sizes[0] / (LSEQ * DIMV);   // 512
    logsig_mma<<<B, THREADS>>>(x, out);
}